// round 3
// baseline (speedup 1.0000x reference)
#include <cuda_runtime.h>
#include <math.h>

// Problem dims (fixed by the reference setup_inputs)
constexpr int Bc = 4;
constexpr int Dc = 128;
constexpr int Hc = 192;
constexpr int Wc = 192;
constexpr int Kc = 11;            // window
constexpr int W1c = Wc - Kc + 1;  // 182
constexpr int H1c = Hc - Kc + 1;  // 182
constexpr int D1c = Dc - Kc + 1;  // 118

constexpr size_t N1C = (size_t)Bc * Dc * Hc * W1c;   // stage-1 output per field
constexpr size_t N2C = (size_t)Bc * Dc * H1c * W1c;  // stage-2 output per field

constexpr float C1f = 0.01f * 0.01f;   // (0.01*L)^2, L=1
constexpr float C2f = 0.03f * 0.03f;

// Scratch: 5 fields per stage. Static __device__ arrays (no allocs allowed).
__device__ float g_s1[5 * N1C];   // ~358 MB
__device__ float g_s2[5 * N2C];   // ~339 MB
__device__ double g_sum;

struct GW { float w[11]; };

// ---------------------------------------------------------------------------
// Stage 1: conv along W + form the 5 products on the fly.
// One block = one (b,d,h) row of 192 elements in smem; 182 outputs.
// ---------------------------------------------------------------------------
__global__ void __launch_bounds__(192) stage1_kernel(
    const float* __restrict__ a, const float* __restrict__ b, GW gw)
{
    __shared__ float s1[Wc];
    __shared__ float s2[Wc];
    const int row = blockIdx.x;            // 0 .. B*D*H-1
    const int tid = threadIdx.x;           // 0 .. 191
    const size_t base = (size_t)row * Wc;
    s1[tid] = a[base + tid];
    s2[tid] = b[base + tid];
    __syncthreads();

    if (tid < W1c) {
        float m1 = 0.f, m2 = 0.f, x11 = 0.f, x22 = 0.f, x12 = 0.f;
#pragma unroll
        for (int k = 0; k < Kc; k++) {
            const float g = gw.w[k];
            const float u = s1[tid + k];
            const float v = s2[tid + k];
            m1  += g * u;
            m2  += g * v;
            x11 += g * u * u;
            x22 += g * v * v;
            x12 += g * u * v;
        }
        const size_t o = (size_t)row * W1c + tid;
        g_s1[o + 0 * N1C] = m1;
        g_s1[o + 1 * N1C] = m2;
        g_s1[o + 2 * N1C] = x11;
        g_s1[o + 3 * N1C] = x22;
        g_s1[o + 4 * N1C] = x12;
    }
}

// ---------------------------------------------------------------------------
// Stage 2: conv along H with register sliding window.
// Thread = (b,d, h-chunk, w). Coalesced along w per tap.
// ---------------------------------------------------------------------------
constexpr int CH2 = 4;                      // h chunks
constexpr int HC2 = (H1c + CH2 - 1) / CH2;  // 46 outputs per chunk

__global__ void __launch_bounds__(192) stage2_kernel(GW gw)
{
    const int w = threadIdx.x;
    if (w >= W1c) return;
    const int blk = blockIdx.x;             // ((b*D + d)*CH2 + c)
    const int c  = blk % CH2;
    const int bd = blk / CH2;               // b*D + d

    const int h0 = c * HC2;
    const int n_out = min(HC2, H1c - h0);

    const size_t inRow = (size_t)bd * Hc * W1c + w;   // + h*W1c

    float win[5][Kc];
#pragma unroll
    for (int k = 0; k < Kc; k++) {
        const size_t idx = inRow + (size_t)(h0 + k) * W1c;
#pragma unroll
        for (int f = 0; f < 5; f++) win[f][k] = g_s1[idx + f * N1C];
    }

    for (int i = 0; i < n_out; i++) {
        float r[5];
#pragma unroll
        for (int f = 0; f < 5; f++) {
            float s = 0.f;
#pragma unroll
            for (int k = 0; k < Kc; k++) s += gw.w[k] * win[f][k];
            r[f] = s;
        }
        const size_t o = ((size_t)bd * H1c + (h0 + i)) * W1c + w;
#pragma unroll
        for (int f = 0; f < 5; f++) g_s2[o + f * N2C] = r[f];

        if (i + 1 < n_out) {
#pragma unroll
            for (int f = 0; f < 5; f++) {
#pragma unroll
                for (int k = 0; k < Kc - 1; k++) win[f][k] = win[f][k + 1];
            }
            const size_t idx = inRow + (size_t)(h0 + i + Kc) * W1c;
#pragma unroll
            for (int f = 0; f < 5; f++) win[f][Kc - 1] = g_s1[idx + f * N1C];
        }
    }
}

// ---------------------------------------------------------------------------
// Stage 3: conv along D + SSIM map + mean reduction (map never materialized).
// Thread = (b, d-chunk, h, w); sliding window over d. Every field byte read once.
// ---------------------------------------------------------------------------
constexpr int CD3 = 2;
constexpr int DC3 = D1c / CD3;   // 59 outputs per chunk (118 = 2*59 exact)

__global__ void __launch_bounds__(192) stage3_kernel(GW gw)
{
    const int w   = threadIdx.x;
    const int blk = blockIdx.x;             // ((b*CD3 + c)*H1 + h)
    const int h   = blk % H1c;
    const int t   = blk / H1c;
    const int c   = t % CD3;
    const int b   = t / CD3;

    double acc = 0.0;

    if (w < W1c) {
        const int d0 = c * DC3;
        const size_t stride = (size_t)H1c * W1c;
        const size_t inCol  = ((size_t)b * Dc * H1c + (size_t)h) * W1c + w; // + d*stride

        float win[5][Kc];
#pragma unroll
        for (int k = 0; k < Kc; k++) {
            const size_t idx = inCol + (size_t)(d0 + k) * stride;
#pragma unroll
            for (int f = 0; f < 5; f++) win[f][k] = g_s2[idx + f * N2C];
        }

        for (int i = 0; i < DC3; i++) {
            float r[5];
#pragma unroll
            for (int f = 0; f < 5; f++) {
                float s = 0.f;
#pragma unroll
                for (int k = 0; k < Kc; k++) s += gw.w[k] * win[f][k];
                r[f] = s;
            }
            const float mu1 = r[0], mu2 = r[1];
            const float x11 = r[2], x22 = r[3], x12 = r[4];
            const float mu1_sq = mu1 * mu1;
            const float mu2_sq = mu2 * mu2;
            const float mu12   = mu1 * mu2;
            const float s1q = x11 - mu1_sq;
            const float s2q = x22 - mu2_sq;
            const float s12 = x12 - mu12;
            const float v1  = 2.0f * s12 + C2f;
            const float v2  = s1q + s2q + C2f;
            const float num = (2.0f * mu12 + C1f) * v1;
            const float den = (mu1_sq + mu2_sq + C1f) * v2;
            acc += (double)(num / den);

            if (i + 1 < DC3) {
#pragma unroll
                for (int f = 0; f < 5; f++) {
#pragma unroll
                    for (int k = 0; k < Kc - 1; k++) win[f][k] = win[f][k + 1];
                }
                const size_t idx = inCol + (size_t)(d0 + i + Kc) * stride;
#pragma unroll
                for (int f = 0; f < 5; f++) win[f][Kc - 1] = g_s2[idx + f * N2C];
            }
        }
    }

    // Block reduction: warp shuffle (exact for 6 warps of 192 threads),
    // then thread 0 sums the 6 warp partials. (The previous tree reduction
    // dropped one partial at the non-power-of-2 fold — 1/3 of the sum.)
    const int lane = threadIdx.x & 31;
    const int wrp  = threadIdx.x >> 5;
#pragma unroll
    for (int off = 16; off > 0; off >>= 1)
        acc += __shfl_down_sync(0xffffffffu, acc, off);

    __shared__ double warp_sum[6];
    if (lane == 0) warp_sum[wrp] = acc;
    __syncthreads();
    if (threadIdx.x == 0) {
        double s = 0.0;
#pragma unroll
        for (int i = 0; i < 6; i++) s += warp_sum[i];
        atomicAdd(&g_sum, s);
    }
}

__global__ void zero_sum_kernel() { g_sum = 0.0; }

__global__ void finalize_kernel(float* __restrict__ out)
{
    constexpr double CNT = (double)Bc * D1c * H1c * W1c;
    out[0] = (float)(g_sum / CNT);
}

// ---------------------------------------------------------------------------
extern "C" void kernel_launch(void* const* d_in, const int* in_sizes, int n_in,
                              void* d_out, int out_size)
{
    const float* img1 = (const float*)d_in[0];
    const float* img2 = (const float*)d_in[1];
    float* out = (float*)d_out;

    // Gaussian weights (sigma=1.5, K=11), normalized like the reference.
    GW gw;
    {
        double g[Kc], s = 0.0;
        for (int k = 0; k < Kc; k++) {
            const double x = (double)k - (double)(Kc / 2);
            g[k] = exp(-(x * x) / (2.0 * 1.5 * 1.5));
            s += g[k];
        }
        s += 1e-12;
        for (int k = 0; k < Kc; k++) gw.w[k] = (float)(g[k] / s);
    }

    stage1_kernel<<<Bc * Dc * Hc, 192>>>(img1, img2, gw);
    stage2_kernel<<<Bc * Dc * CH2, 192>>>(gw);
    zero_sum_kernel<<<1, 1>>>();
    stage3_kernel<<<Bc * CD3 * H1c, 192>>>(gw);
    finalize_kernel<<<1, 1>>>(out);
}

// round 8
// speedup vs baseline: 1.5060x; 1.5060x over previous
#include <cuda_runtime.h>
#include <math.h>

// Problem dims (fixed by the reference setup_inputs)
constexpr int Bc = 4;
constexpr int Dc = 128;
constexpr int Hc = 192;
constexpr int Wc = 192;
constexpr int Kc = 11;            // window
constexpr int W1c = Wc - Kc + 1;  // 182
constexpr int H1c = Hc - Kc + 1;  // 182
constexpr int D1c = Dc - Kc + 1;  // 118

constexpr size_t N2C = (size_t)Bc * Dc * H1c * W1c;  // fused stage-1/2 output per field

constexpr float C1f = 0.01f * 0.01f;   // (0.01*L)^2, L=1
constexpr float C2f = 0.03f * 0.03f;

// Scratch: 5 fields (mu1, mu2, E[x1^2], E[x2^2], E[x1*x2]) after W+H conv.
__device__ float g_s2[5 * N2C];   // ~339 MB
__device__ double g_sum;

struct GW { float w[11]; };

// ---- packed f32x2 helpers (sm_103a FFMA2 — only reachable via PTX) -------
typedef unsigned long long u64v;
__device__ __forceinline__ u64v pack2(float lo, float hi) {
    u64v r; asm("mov.b64 %0, {%1, %2};" : "=l"(r) : "f"(lo), "f"(hi)); return r;
}
__device__ __forceinline__ void unpack2(u64v v, float& lo, float& hi) {
    asm("mov.b64 {%0, %1}, %2;" : "=f"(lo), "=f"(hi) : "l"(v));
}
__device__ __forceinline__ u64v fma2(u64v a, u64v b, u64v c) {
    u64v d; asm("fma.rn.f32x2 %0, %1, %2, %3;" : "=l"(d) : "l"(a), "l"(b), "l"(c)); return d;
}
__device__ __forceinline__ u64v mul2(u64v a, u64v b) {
    u64v d; asm("mul.rn.f32x2 %0, %1, %2;" : "=l"(d) : "l"(a), "l"(b)); return d;
}

// ---------------------------------------------------------------------------
// Fused stage 1+2: W-conv (+ product formation) and H-conv in one pass.
// Block = one (b,d) slice, 192 threads (thread = w). For each image row h:
// load row to smem (double-buffered, one sync per row), compute the 5-field
// W-conv at this thread's w, push into a per-thread register sliding window
// along h (H-conv only ever needs same-w values), and once 11 rows are live
// emit the H-conv output for h-10. (mu1,mu2) and (x11,x22) ride f32x2 lanes.
// ---------------------------------------------------------------------------
__global__ void __launch_bounds__(192) stage12_kernel(
    const float* __restrict__ a, const float* __restrict__ b, GW gw)
{
    __shared__ float s1[2][Wc];
    __shared__ float s2[2][Wc];
    const int bd  = blockIdx.x;            // b*D + d
    const int tid = threadIdx.x;           // w

    u64v g2[Kc];
#pragma unroll
    for (int k = 0; k < Kc; k++) g2[k] = pack2(gw.w[k], gw.w[k]);

    const float* __restrict__ ar = a + (size_t)bd * Hc * Wc;
    const float* __restrict__ br = b + (size_t)bd * Hc * Wc;
    const size_t outBase = (size_t)bd * H1c * W1c + tid;

    u64v wm[Kc], wx[Kc];     // packed (mu1,mu2) and (x11,x22) H-windows
    float w12[Kc];           // x12 H-window
#pragma unroll
    for (int k = 0; k < Kc; k++) { wm[k] = 0; wx[k] = 0; w12[k] = 0.f; }

    for (int h = 0; h < Hc; h++) {
        const int buf = h & 1;
        s1[buf][tid] = ar[h * Wc + tid];
        s2[buf][tid] = br[h * Wc + tid];
        __syncthreads();

        u64v m12 = 0, x1122 = 0; float x12 = 0.f;
        if (tid < W1c) {
#pragma unroll
            for (int k = 0; k < Kc; k++) {
                const float u = s1[buf][tid + k];
                const float v = s2[buf][tid + k];
                const u64v uv = pack2(u, v);
                m12   = fma2(g2[k], uv, m12);          // (g*u, g*v)
                x1122 = fma2(g2[k], mul2(uv, uv), x1122); // (g*u^2, g*v^2)
                x12   = fmaf(gw.w[k] * u, v, x12);     // g*u*v
            }
        }

        // slide H-window, insert newest row
#pragma unroll
        for (int k = 0; k < Kc - 1; k++) {
            wm[k] = wm[k + 1]; wx[k] = wx[k + 1]; w12[k] = w12[k + 1];
        }
        wm[Kc - 1] = m12; wx[Kc - 1] = x1122; w12[Kc - 1] = x12;

        if (h >= Kc - 1 && tid < W1c) {
            u64v cm = 0, cx = 0; float c12 = 0.f;
#pragma unroll
            for (int k = 0; k < Kc; k++) {
                cm  = fma2(g2[k], wm[k], cm);
                cx  = fma2(g2[k], wx[k], cx);
                c12 = fmaf(gw.w[k], w12[k], c12);
            }
            float m1, m2, x11, x22;
            unpack2(cm, m1, m2);
            unpack2(cx, x11, x22);
            const size_t o = outBase + (size_t)(h - (Kc - 1)) * W1c;
            g_s2[o + 0 * N2C] = m1;
            g_s2[o + 1 * N2C] = m2;
            g_s2[o + 2 * N2C] = x11;
            g_s2[o + 3 * N2C] = x22;
            g_s2[o + 4 * N2C] = c12;
        }
    }
}

// ---------------------------------------------------------------------------
// Stage 3: conv along D + SSIM map + mean reduction (map never materialized).
// Thread = (b, d-chunk, h, w); sliding window over d with distance-1 prefetch
// so the 5 gmem loads overlap the conv/SSIM compute of the current step.
// ---------------------------------------------------------------------------
constexpr int CD3 = 4;
constexpr int DC3 = (D1c + CD3 - 1) / CD3;   // 30 (last chunk 28)

__global__ void __launch_bounds__(192) stage3_kernel(GW gw)
{
    const int w   = threadIdx.x;
    const int blk = blockIdx.x;             // ((b*CD3 + c)*H1 + h)
    const int h   = blk % H1c;
    const int t   = blk / H1c;
    const int c   = t % CD3;
    const int b   = t / CD3;

    double acc = 0.0;

    if (w < W1c) {
        const int d0 = c * DC3;
        const int n_out = min(DC3, D1c - d0);
        const size_t stride = (size_t)H1c * W1c;
        const size_t inCol  = ((size_t)b * Dc * H1c + (size_t)h) * W1c + w;

        float win[5][Kc];
#pragma unroll
        for (int k = 0; k < Kc; k++) {
            const size_t idx = inCol + (size_t)(d0 + k) * stride;
#pragma unroll
            for (int f = 0; f < 5; f++) win[f][k] = g_s2[idx + f * N2C];
        }

        for (int i = 0; i < n_out; i++) {
            const bool more = (i + 1 < n_out);
            float nxt[5];
            if (more) {       // issue next-slice loads BEFORE the compute
                const size_t idx = inCol + (size_t)(d0 + i + Kc) * stride;
#pragma unroll
                for (int f = 0; f < 5; f++) nxt[f] = g_s2[idx + f * N2C];
            }

            float r[5];
#pragma unroll
            for (int f = 0; f < 5; f++) {
                float s = 0.f;
#pragma unroll
                for (int k = 0; k < Kc; k++) s += gw.w[k] * win[f][k];
                r[f] = s;
            }
            const float mu1 = r[0], mu2 = r[1];
            const float x11 = r[2], x22 = r[3], x12 = r[4];
            const float mu1_sq = mu1 * mu1;
            const float mu2_sq = mu2 * mu2;
            const float mu12   = mu1 * mu2;
            const float s1q = x11 - mu1_sq;
            const float s2q = x22 - mu2_sq;
            const float s12 = x12 - mu12;
            const float v1  = 2.0f * s12 + C2f;
            const float v2  = s1q + s2q + C2f;
            const float num = (2.0f * mu12 + C1f) * v1;
            const float den = (mu1_sq + mu2_sq + C1f) * v2;
            acc += (double)(num / den);

            if (more) {
#pragma unroll
                for (int f = 0; f < 5; f++) {
#pragma unroll
                    for (int k = 0; k < Kc - 1; k++) win[f][k] = win[f][k + 1];
                    win[f][Kc - 1] = nxt[f];
                }
            }
        }
    }

    // Block reduction: warp shuffle (exact for 6 warps), double atomic once.
    const int lane = threadIdx.x & 31;
    const int wrp  = threadIdx.x >> 5;
#pragma unroll
    for (int off = 16; off > 0; off >>= 1)
        acc += __shfl_down_sync(0xffffffffu, acc, off);

    __shared__ double warp_sum[6];
    if (lane == 0) warp_sum[wrp] = acc;
    __syncthreads();
    if (threadIdx.x == 0) {
        double s = 0.0;
#pragma unroll
        for (int i = 0; i < 6; i++) s += warp_sum[i];
        atomicAdd(&g_sum, s);
    }
}

__global__ void zero_sum_kernel() { g_sum = 0.0; }

__global__ void finalize_kernel(float* __restrict__ out)
{
    constexpr double CNT = (double)Bc * D1c * H1c * W1c;
    out[0] = (float)(g_sum / CNT);
}

// ---------------------------------------------------------------------------
extern "C" void kernel_launch(void* const* d_in, const int* in_sizes, int n_in,
                              void* d_out, int out_size)
{
    const float* img1 = (const float*)d_in[0];
    const float* img2 = (const float*)d_in[1];
    float* out = (float*)d_out;

    // Gaussian weights (sigma=1.5, K=11), normalized like the reference.
    GW gw;
    {
        double g[Kc], s = 0.0;
        for (int k = 0; k < Kc; k++) {
            const double x = (double)k - (double)(Kc / 2);
            g[k] = exp(-(x * x) / (2.0 * 1.5 * 1.5));
            s += g[k];
        }
        s += 1e-12;
        for (int k = 0; k < Kc; k++) gw.w[k] = (float)(g[k] / s);
    }

    stage12_kernel<<<Bc * Dc, 192>>>(img1, img2, gw);
    zero_sum_kernel<<<1, 1>>>();
    stage3_kernel<<<Bc * CD3 * H1c, 192>>>(gw);
    finalize_kernel<<<1, 1>>>(out);
}

// round 13
// speedup vs baseline: 1.6064x; 1.0666x over previous
#include <cuda_runtime.h>
#include <math.h>

// Problem dims (fixed by the reference setup_inputs)
constexpr int Bc = 4;
constexpr int Dc = 128;
constexpr int Hc = 192;
constexpr int Wc = 192;
constexpr int Kc = 11;            // window
constexpr int W1c = Wc - Kc + 1;  // 182
constexpr int H1c = Hc - Kc + 1;  // 182
constexpr int D1c = Dc - Kc + 1;  // 118

constexpr size_t N2C = (size_t)Bc * Dc * H1c * W1c;  // intermediate voxels

constexpr float C1f = 0.01f * 0.01f;   // (0.01*L)^2, L=1
constexpr float C2f = 0.03f * 0.03f;

// Intermediate after W+H conv: float4 (mu1, mu2, x11, x22) + float (x12).
__device__ float4 g_q4[N2C];   // ~271 MB
__device__ float  g_q1[N2C];   // ~68 MB
__device__ double g_sum;

struct GW { float w[11]; };

// ---- packed f32x2 helpers (sm_103a FFMA2 — only reachable via PTX) -------
typedef unsigned long long u64v;
__device__ __forceinline__ u64v pack2(float lo, float hi) {
    u64v r; asm("mov.b64 %0, {%1, %2};" : "=l"(r) : "f"(lo), "f"(hi)); return r;
}
__device__ __forceinline__ void unpack2(u64v v, float& lo, float& hi) {
    asm("mov.b64 {%0, %1}, %2;" : "=f"(lo), "=f"(hi) : "l"(v));
}
__device__ __forceinline__ u64v fma2(u64v a, u64v b, u64v c) {
    u64v d; asm("fma.rn.f32x2 %0, %1, %2, %3;" : "=l"(d) : "l"(a), "l"(b), "l"(c)); return d;
}
__device__ __forceinline__ u64v mul2(u64v a, u64v b) {
    u64v d; asm("mul.rn.f32x2 %0, %1, %2;" : "=l"(d) : "l"(a), "l"(b)); return d;
}

// ---------------------------------------------------------------------------
// Fused stage 1+2: W-conv (+ products) and H-conv in one pass.
// Block = (b,d, h-chunk): 4 chunks per slice (46 output rows from 56 input
// rows, 10-row halo). 2048 blocks total — 4x the parallelism of the
// one-block-per-slice version, serial chain 192 -> 56 iterations.
// ---------------------------------------------------------------------------
constexpr int CH12 = 4;
constexpr int HC12 = (H1c + CH12 - 1) / CH12;   // 46

__global__ void __launch_bounds__(192) stage12_kernel(
    const float* __restrict__ a, const float* __restrict__ b, GW gw)
{
    __shared__ float s1[2][Wc];
    __shared__ float s2[2][Wc];
    const int blk = blockIdx.x;            // bd*CH12 + c
    const int c   = blk % CH12;
    const int bd  = blk / CH12;            // b*D + d
    const int tid = threadIdx.x;           // w

    const int h0    = c * HC12;
    const int n_out = min(HC12, H1c - h0);      // 46 or 44
    const int n_in  = n_out + Kc - 1;           // rows to stream

    u64v g2[Kc];
#pragma unroll
    for (int k = 0; k < Kc; k++) g2[k] = pack2(gw.w[k], gw.w[k]);

    const float* __restrict__ ar = a + (size_t)bd * Hc * Wc;
    const float* __restrict__ br = b + (size_t)bd * Hc * Wc;
    const size_t outBase = (size_t)bd * H1c * W1c + tid;

    u64v wm[Kc], wx[Kc];     // packed (mu1,mu2) and (x11,x22) H-windows
    float w12[Kc];           // x12 H-window
#pragma unroll
    for (int k = 0; k < Kc; k++) { wm[k] = 0; wx[k] = 0; w12[k] = 0.f; }

    for (int hh = 0; hh < n_in; hh++) {
        const int h   = h0 + hh;           // input row
        const int buf = hh & 1;
        s1[buf][tid] = ar[h * Wc + tid];
        s2[buf][tid] = br[h * Wc + tid];
        __syncthreads();

        u64v m12 = 0, x1122 = 0; float x12 = 0.f;
        if (tid < W1c) {
#pragma unroll
            for (int k = 0; k < Kc; k++) {
                const float u = s1[buf][tid + k];
                const float v = s2[buf][tid + k];
                const u64v uv = pack2(u, v);
                m12   = fma2(g2[k], uv, m12);             // (g*u, g*v)
                x1122 = fma2(g2[k], mul2(uv, uv), x1122); // (g*u^2, g*v^2)
                x12   = fmaf(gw.w[k] * u, v, x12);        // g*u*v
            }
        }

        // slide H-window, insert newest row
#pragma unroll
        for (int k = 0; k < Kc - 1; k++) {
            wm[k] = wm[k + 1]; wx[k] = wx[k + 1]; w12[k] = w12[k + 1];
        }
        wm[Kc - 1] = m12; wx[Kc - 1] = x1122; w12[Kc - 1] = x12;

        if (hh >= Kc - 1 && tid < W1c) {
            u64v cm = 0, cx = 0; float c12 = 0.f;
#pragma unroll
            for (int k = 0; k < Kc; k++) {
                cm  = fma2(g2[k], wm[k], cm);
                cx  = fma2(g2[k], wx[k], cx);
                c12 = fmaf(gw.w[k], w12[k], c12);
            }
            float4 q;
            unpack2(cm, q.x, q.y);    // mu1, mu2
            unpack2(cx, q.z, q.w);    // x11, x22
            const size_t o = outBase + (size_t)(h0 + hh - (Kc - 1)) * W1c;
            g_q4[o] = q;              // STG.128
            g_q1[o] = c12;            // STG.32
        }
    }
}

// ---------------------------------------------------------------------------
// Stage 3: conv along D + SSIM map + mean reduction (map never materialized).
// Thread = (b, d-chunk, h, w); sliding window over d; per d-step only TWO
// loads (LDG.128 + LDG.32) thanks to the packed layout, issued before the
// compute so they overlap a full conv iteration.
// ---------------------------------------------------------------------------
constexpr int CD3 = 4;
constexpr int DC3 = (D1c + CD3 - 1) / CD3;   // 30 (last chunk 28)

__global__ void __launch_bounds__(192) stage3_kernel(GW gw)
{
    const int w   = threadIdx.x;
    const int blk = blockIdx.x;             // ((b*CD3 + c)*H1 + h)
    const int h   = blk % H1c;
    const int t   = blk / H1c;
    const int c   = t % CD3;
    const int b   = t / CD3;

    double acc = 0.0;

    if (w < W1c) {
        u64v g2[Kc];
#pragma unroll
        for (int k = 0; k < Kc; k++) g2[k] = pack2(gw.w[k], gw.w[k]);

        const int d0 = c * DC3;
        const int n_out = min(DC3, D1c - d0);
        const size_t stride = (size_t)H1c * W1c;
        const size_t inCol  = ((size_t)b * Dc * H1c + (size_t)h) * W1c + w;

        float4 win4[Kc]; float win1[Kc];
#pragma unroll
        for (int k = 0; k < Kc; k++) {
            const size_t idx = inCol + (size_t)(d0 + k) * stride;
            win4[k] = g_q4[idx];
            win1[k] = g_q1[idx];
        }

        for (int i = 0; i < n_out; i++) {
            const bool more = (i + 1 < n_out);
            float4 nxt4; float nxt1;
            if (more) {       // issue next-slice loads BEFORE the compute
                const size_t idx = inCol + (size_t)(d0 + i + Kc) * stride;
                nxt4 = g_q4[idx];
                nxt1 = g_q1[idx];
            }

            // conv: packed halves of the float4 ride f32x2 lanes
            u64v cm = 0, cx = 0; float c12 = 0.f;
#pragma unroll
            for (int k = 0; k < Kc; k++) {
                cm  = fma2(g2[k], pack2(win4[k].x, win4[k].y), cm);
                cx  = fma2(g2[k], pack2(win4[k].z, win4[k].w), cx);
                c12 = fmaf(gw.w[k], win1[k], c12);
            }
            float mu1, mu2, x11, x22;
            unpack2(cm, mu1, mu2);
            unpack2(cx, x11, x22);

            const float mu1_sq = mu1 * mu1;
            const float mu2_sq = mu2 * mu2;
            const float mu12   = mu1 * mu2;
            const float s1q = x11 - mu1_sq;
            const float s2q = x22 - mu2_sq;
            const float s12 = c12 - mu12;
            const float v1  = 2.0f * s12 + C2f;
            const float v2  = s1q + s2q + C2f;
            const float num = (2.0f * mu12 + C1f) * v1;
            const float den = (mu1_sq + mu2_sq + C1f) * v2;
            acc += (double)(num / den);

            if (more) {
#pragma unroll
                for (int k = 0; k < Kc - 1; k++) {
                    win4[k] = win4[k + 1]; win1[k] = win1[k + 1];
                }
                win4[Kc - 1] = nxt4; win1[Kc - 1] = nxt1;
            }
        }
    }

    // Block reduction: warp shuffle (exact for 6 warps), double atomic once.
    const int lane = threadIdx.x & 31;
    const int wrp  = threadIdx.x >> 5;
#pragma unroll
    for (int off = 16; off > 0; off >>= 1)
        acc += __shfl_down_sync(0xffffffffu, acc, off);

    __shared__ double warp_sum[6];
    if (lane == 0) warp_sum[wrp] = acc;
    __syncthreads();
    if (threadIdx.x == 0) {
        double s = 0.0;
#pragma unroll
        for (int i = 0; i < 6; i++) s += warp_sum[i];
        atomicAdd(&g_sum, s);
    }
}

__global__ void zero_sum_kernel() { g_sum = 0.0; }

__global__ void finalize_kernel(float* __restrict__ out)
{
    constexpr double CNT = (double)Bc * D1c * H1c * W1c;
    out[0] = (float)(g_sum / CNT);
}

// ---------------------------------------------------------------------------
extern "C" void kernel_launch(void* const* d_in, const int* in_sizes, int n_in,
                              void* d_out, int out_size)
{
    const float* img1 = (const float*)d_in[0];
    const float* img2 = (const float*)d_in[1];
    float* out = (float*)d_out;

    // Gaussian weights (sigma=1.5, K=11), normalized like the reference.
    GW gw;
    {
        double g[Kc], s = 0.0;
        for (int k = 0; k < Kc; k++) {
            const double x = (double)k - (double)(Kc / 2);
            g[k] = exp(-(x * x) / (2.0 * 1.5 * 1.5));
            s += g[k];
        }
        s += 1e-12;
        for (int k = 0; k < Kc; k++) gw.w[k] = (float)(g[k] / s);
    }

    stage12_kernel<<<Bc * Dc * CH12, 192>>>(img1, img2, gw);
    zero_sum_kernel<<<1, 1>>>();
    stage3_kernel<<<Bc * CD3 * H1c, 192>>>(gw);
    finalize_kernel<<<1, 1>>>(out);
}